// round 14
// baseline (speedup 1.0000x reference)
#include <cuda_runtime.h>
#include <cuda_fp16.h>
#include <cstdint>

// BinarizedLinear: out[M,N] = x[M,K] @ sign(W)[N,K]^T + bias[N]
// M=8192, N=4096, K=4096, fp32 in/out.
//
// sm_103 (non-'a') PTX target -> no tcgen05; legacy mma.sync path.
// fp16 data (sign(W) exact; x rounded -> rel_err ~2e-4, fp32 accum).
//
// Round 14 = R13 mainloop (best, 634.7us; tensor=77.4%) made PERSISTENT:
// 296 CTAs (2/SM), each walks its tiles over one linear cp.async stage
// stream, so next-tile loads are in flight while the current tile's last
// stages compute and while its epilogue stores. Removes per-CTA pipeline
// fills and hides the epilogue. Wait/commit accounting identical to R13.

#define M_DIM 8192
#define N_DIM 4096
#define K_DIM 4096

#define BM 128
#define BN 128
#define BK 64
#define STAGES 3
#define KTILES (K_DIM / BK)          // 64
#define NTHREADS 256
#define NTILES ((M_DIM / BM) * (N_DIM / BN))   // 2048
#define NCTAS 296                    // 2 per SM * 148 SMs
#define TILES_N (N_DIM / BN)         // 32

// fp16 scratch (allocation-free: __device__ globals)
__device__ __half g_A[(size_t)M_DIM * K_DIM];   // 64 MB
__device__ __half g_B[(size_t)N_DIM * K_DIM];   // 32 MB

// ---------------------------------------------------------------------------
// Merged conversion kernel: x -> fp16 (g_A), sign(w) -> fp16 (g_B)
// ---------------------------------------------------------------------------

__device__ __forceinline__ float signf_strict(float v) {
    return (v > 0.0f) ? 1.0f : ((v < 0.0f) ? -1.0f : 0.0f);
}

__global__ void convert_both_kernel(const float* __restrict__ x,
                                    const float* __restrict__ w) {
    const size_t n4x = (size_t)M_DIM * K_DIM / 4;
    const size_t n4w = (size_t)N_DIM * K_DIM / 4;
    const size_t total = n4x + n4w;
    const float4* inx = (const float4*)x;
    const float4* inw = (const float4*)w;
    uint2* outa = (uint2*)g_A;
    uint2* outb = (uint2*)g_B;
    for (size_t i = (size_t)blockIdx.x * blockDim.x + threadIdx.x; i < total;
         i += (size_t)gridDim.x * blockDim.x) {
        if (i < n4x) {
            float4 v = inx[i];
            __half2 h0 = __floats2half2_rn(v.x, v.y);
            __half2 h1 = __floats2half2_rn(v.z, v.w);
            uint2 o;
            o.x = *reinterpret_cast<uint32_t*>(&h0);
            o.y = *reinterpret_cast<uint32_t*>(&h1);
            outa[i] = o;
        } else {
            size_t j = i - n4x;
            float4 v = inw[j];
            __half2 h0 = __floats2half2_rn(signf_strict(v.x), signf_strict(v.y));
            __half2 h1 = __floats2half2_rn(signf_strict(v.z), signf_strict(v.w));
            uint2 o;
            o.x = *reinterpret_cast<uint32_t*>(&h0);
            o.y = *reinterpret_cast<uint32_t*>(&h1);
            outb[j] = o;
        }
    }
}

// ---------------------------------------------------------------------------
// GEMM kernel (persistent)
// ---------------------------------------------------------------------------
// CTA tile: 128(M) x 128(N) x 64(K). 256 threads = 8 warps in 2(M) x 4(N).
// Warp tile: 64 x 32 -> 4(m16) x 4(n8) = 16 mma.m16n8k16 per k16 step.
// SMEM: rows of 64 halves = 128 bytes; SW128 swizzle (seg ^= row&7).
// 3 stages x 32KB = 96KB -> 2 CTAs/SM (RF cap: 2 x 256 x 128 regs).

#define A_STAGE_BYTES (BM * 128)              // 16 KB
#define B_STAGE_BYTES (BN * 128)              // 16 KB
#define STAGE_BYTES   (A_STAGE_BYTES + B_STAGE_BYTES)  // 32 KB
#define SMEM_BYTES    (STAGES * STAGE_BYTES)  // 96 KB

__global__ void __launch_bounds__(NTHREADS, 2)
binlinear_gemm_kernel(const float* __restrict__ bias, float* __restrict__ out) {
    extern __shared__ char smem[];
    uint32_t smem_u32;
    asm("{ .reg .u64 t; cvta.to.shared.u64 t, %1; cvt.u32.u64 %0, t; }"
        : "=r"(smem_u32) : "l"(smem));

    const int tid  = threadIdx.x;
    const int lane = tid & 31;
    const int wid  = tid >> 5;
    const int warp_m = (wid >> 2) * 64;   // 0 or 64
    const int warp_n = (wid & 3) * 32;    // 0,32,64,96

    const int cta = blockIdx.x;

    // Tiles for this CTA: cta, cta+NCTAS, ... ; tile t -> n-idx t%32, m-idx t/32.
    const int my_ntiles = (NTILES - cta + NCTAS - 1) / NCTAS;
    const int total_ls  = my_ntiles * KTILES;

    // Per-thread fixed load geometry: chunk i handles cid = tid + i*256.
    int c_row[4], c_seg[4];
    uint32_t c_dst[4];
#pragma unroll
    for (int i = 0; i < 4; ++i) {
        int cid = tid + i * NTHREADS;
        c_row[i] = cid >> 3;
        c_seg[i] = cid & 7;
        c_dst[i] = (uint32_t)c_row[i] * 128 + ((c_seg[i] ^ (c_row[i] & 7)) << 4);
    }

    // Issue the 8 cp.async for linear stage index ls (tile = ls>>6, kt = ls&63).
    auto load_ls = [&](int ls) {
        const int t_loc = ls >> 6;
        const int kt    = ls & 63;
        const int tile  = cta + t_loc * NCTAS;
        const int lm0   = (tile >> 5) * BM;          // tile / 32
        const int ln0   = (tile & 31) * BN;          // tile % 32
        const int slot  = ls % STAGES;
        const uint32_t a_base = smem_u32 + slot * STAGE_BYTES;
        const uint32_t b_base = a_base + A_STAGE_BYTES;
        const __half* gA = g_A + (size_t)lm0 * K_DIM + kt * BK;
        const __half* gB = g_B + (size_t)ln0 * K_DIM + kt * BK;
#pragma unroll
        for (int i = 0; i < 4; ++i) {
            const __half* src = gA + (size_t)c_row[i] * K_DIM + c_seg[i] * 8;
            asm volatile("cp.async.cg.shared.global [%0], [%1], 16;\n"
                         :: "r"(a_base + c_dst[i]), "l"(src));
        }
#pragma unroll
        for (int i = 0; i < 4; ++i) {
            const __half* src = gB + (size_t)c_row[i] * K_DIM + c_seg[i] * 8;
            asm volatile("cp.async.cg.shared.global [%0], [%1], 16;\n"
                         :: "r"(b_base + c_dst[i]), "l"(src));
        }
    };

    // ---- ldmatrix lane addressing -----------------------------------------
    const int a_g  = lane >> 3;
    const int a_row_in = (lane & 7) + (a_g & 1) * 8;
    const int a_hi = a_g >> 1;
    const int b_row_in = (lane & 7) + ((a_g >> 1) & 1) * 8;
    const int b_hi = a_g & 1;
    const int sxor = lane & 7;

    uint32_t a_row_off[4];
#pragma unroll
    for (int mi = 0; mi < 4; ++mi)
        a_row_off[mi] = (uint32_t)(warp_m + mi * 16 + a_row_in) * 128;
    uint32_t b_row_off[2];
#pragma unroll
    for (int nj = 0; nj < 2; ++nj)
        b_row_off[nj] = (uint32_t)(warp_n + nj * 16 + b_row_in) * 128;

    float acc[4][4][4];
#pragma unroll
    for (int mi = 0; mi < 4; ++mi)
#pragma unroll
        for (int nk = 0; nk < 4; ++nk)
#pragma unroll
            for (int r = 0; r < 4; ++r) acc[mi][nk][r] = 0.0f;

    // ---- one k16 compute step ---------------------------------------------
    auto compute_ks = [&](uint32_t a_base, uint32_t b_base, int ks) {
        uint32_t af[4][4];
        uint32_t bf[2][4];
#pragma unroll
        for (int mi = 0; mi < 4; ++mi) {
            uint32_t addr = a_base + a_row_off[mi]
                          + ((uint32_t)((ks * 2 + a_hi) ^ sxor) << 4);
            asm volatile(
                "ldmatrix.sync.aligned.m8n8.x4.shared.b16 {%0,%1,%2,%3}, [%4];\n"
                : "=r"(af[mi][0]), "=r"(af[mi][1]),
                  "=r"(af[mi][2]), "=r"(af[mi][3])
                : "r"(addr));
        }
#pragma unroll
        for (int nj = 0; nj < 2; ++nj) {
            uint32_t addr = b_base + b_row_off[nj]
                          + ((uint32_t)((ks * 2 + b_hi) ^ sxor) << 4);
            asm volatile(
                "ldmatrix.sync.aligned.m8n8.x4.shared.b16 {%0,%1,%2,%3}, [%4];\n"
                : "=r"(bf[nj][0]), "=r"(bf[nj][1]),
                  "=r"(bf[nj][2]), "=r"(bf[nj][3])
                : "r"(addr));
        }
#pragma unroll
        for (int mi = 0; mi < 4; ++mi) {
#pragma unroll
            for (int nk = 0; nk < 4; ++nk) {
                const int nj = nk >> 1;
                const int sub = (nk & 1) * 2;
                asm volatile(
                    "mma.sync.aligned.m16n8k16.row.col.f32.f16.f16.f32 "
                    "{%0,%1,%2,%3}, {%4,%5,%6,%7}, {%8,%9}, {%0,%1,%2,%3};\n"
                    : "+f"(acc[mi][nk][0]), "+f"(acc[mi][nk][1]),
                      "+f"(acc[mi][nk][2]), "+f"(acc[mi][nk][3])
                    : "r"(af[mi][0]), "r"(af[mi][1]),
                      "r"(af[mi][2]), "r"(af[mi][3]),
                      "r"(bf[nj][sub]), "r"(bf[nj][sub + 1]));
            }
        }
    };

    // ---- prologue: first 2 linear stages ----------------------------------
    load_ls(0);
    asm volatile("cp.async.commit_group;\n");
    if (total_ls > 1) load_ls(1);
    asm volatile("cp.async.commit_group;\n");

    // ---- persistent mainloop ----------------------------------------------
    for (int ls = 0; ls < total_ls; ++ls) {
        asm volatile("cp.async.wait_group %0;\n" :: "n"(STAGES - 2));
        __syncthreads();

        const int slot = ls % STAGES;
        const uint32_t a_base = smem_u32 + slot * STAGE_BYTES;
        const uint32_t b_base = a_base + A_STAGE_BYTES;

        // ks=0, then next-stage loads (commit immediately: R13 accounting),
        // then remaining k-steps.
        compute_ks(a_base, b_base, 0);

        const int ld = ls + STAGES - 1;
        if (ld < total_ls) load_ls(ld);
        asm volatile("cp.async.commit_group;\n");

        compute_ks(a_base, b_base, 1);
        compute_ks(a_base, b_base, 2);
        compute_ks(a_base, b_base, 3);

        // ---- per-tile epilogue (overlaps next tile's in-flight loads) -----
        if ((ls & 63) == 63) {
            const int tile = cta + (ls >> 6) * NCTAS;
            const int m0 = (tile >> 5) * BM;
            const int n0 = (tile & 31) * BN;
#pragma unroll
            for (int mi = 0; mi < 4; ++mi) {
                const int r0 = m0 + warp_m + mi * 16 + (lane >> 2);
#pragma unroll
                for (int nk = 0; nk < 4; ++nk) {
                    const int c = n0 + warp_n + nk * 8 + (lane & 3) * 2;
                    const float b0 = bias[c];
                    const float b1 = bias[c + 1];
                    float2 v;
                    v.x = acc[mi][nk][0] + b0;
                    v.y = acc[mi][nk][1] + b1;
                    *reinterpret_cast<float2*>(&out[(size_t)r0 * N_DIM + c]) = v;
                    v.x = acc[mi][nk][2] + b0;
                    v.y = acc[mi][nk][3] + b1;
                    *reinterpret_cast<float2*>(&out[(size_t)(r0 + 8) * N_DIM + c]) = v;
#pragma unroll
                    for (int r = 0; r < 4; ++r) acc[mi][nk][r] = 0.0f;
                }
            }
        }
    }
}

// ---------------------------------------------------------------------------
// Launch
// ---------------------------------------------------------------------------

extern "C" void kernel_launch(void* const* d_in, const int* in_sizes, int n_in,
                              void* d_out, int out_size) {
    const float* x    = (const float*)d_in[0];
    const float* w    = (const float*)d_in[1];
    const float* bias = (const float*)d_in[2];
    float* out        = (float*)d_out;

    convert_both_kernel<<<3072, 256>>>(x, w);

    cudaFuncSetAttribute(binlinear_gemm_kernel,
                         cudaFuncAttributeMaxDynamicSharedMemorySize,
                         SMEM_BYTES);

    binlinear_gemm_kernel<<<NCTAS, NTHREADS, SMEM_BYTES>>>(bias, out);
}

// round 15
// speedup vs baseline: 1.0986x; 1.0986x over previous
#include <cuda_runtime.h>
#include <cuda_fp16.h>
#include <cstdint>

// BinarizedLinear: out[M,N] = x[M,K] @ sign(W)[N,K]^T + bias[N]
// M=8192, N=4096, K=4096, fp32 in/out.
//
// sm_103 (non-'a') PTX target -> no tcgen05; legacy mma.sync path.
// fp16 data (sign(W) exact; x rounded -> rel_err ~2e-4, fp32 accum).
//
// Round 15 = R13 (best, 634.7us; tensor=77.4%) with ONE change: compute_ks
// is software-pipelined internally. Old order: 6 ldmatrix then 16 MMAs
// (full LDS-return chain exposed at every k-step boundary). New order:
// bf0,bf1,af0 up front, then each mi's 4-MMA block (~32cyc) shadows the
// ldmatrix for af[mi+1]. Zero extra registers -> 2 CTAs/SM preserved.
// (R14 post-mortem: persistence regressed -- dynamic indexing + in-loop
// epilogue cost more than per-CTA pipeline fills saved; reverted.)

#define M_DIM 8192
#define N_DIM 4096
#define K_DIM 4096

#define BM 128
#define BN 128
#define BK 64
#define STAGES 3
#define KTILES (K_DIM / BK)   // 64
#define NTHREADS 256

// fp16 scratch (allocation-free: __device__ globals)
__device__ __half g_A[(size_t)M_DIM * K_DIM];   // 64 MB
__device__ __half g_B[(size_t)N_DIM * K_DIM];   // 32 MB

// ---------------------------------------------------------------------------
// Merged conversion kernel: x -> fp16 (g_A), sign(w) -> fp16 (g_B)
// ---------------------------------------------------------------------------

__device__ __forceinline__ float signf_strict(float v) {
    return (v > 0.0f) ? 1.0f : ((v < 0.0f) ? -1.0f : 0.0f);
}

__global__ void convert_both_kernel(const float* __restrict__ x,
                                    const float* __restrict__ w) {
    const size_t n4x = (size_t)M_DIM * K_DIM / 4;
    const size_t n4w = (size_t)N_DIM * K_DIM / 4;
    const size_t total = n4x + n4w;
    const float4* inx = (const float4*)x;
    const float4* inw = (const float4*)w;
    uint2* outa = (uint2*)g_A;
    uint2* outb = (uint2*)g_B;
    for (size_t i = (size_t)blockIdx.x * blockDim.x + threadIdx.x; i < total;
         i += (size_t)gridDim.x * blockDim.x) {
        if (i < n4x) {
            float4 v = inx[i];
            __half2 h0 = __floats2half2_rn(v.x, v.y);
            __half2 h1 = __floats2half2_rn(v.z, v.w);
            uint2 o;
            o.x = *reinterpret_cast<uint32_t*>(&h0);
            o.y = *reinterpret_cast<uint32_t*>(&h1);
            outa[i] = o;
        } else {
            size_t j = i - n4x;
            float4 v = inw[j];
            __half2 h0 = __floats2half2_rn(signf_strict(v.x), signf_strict(v.y));
            __half2 h1 = __floats2half2_rn(signf_strict(v.z), signf_strict(v.w));
            uint2 o;
            o.x = *reinterpret_cast<uint32_t*>(&h0);
            o.y = *reinterpret_cast<uint32_t*>(&h1);
            outb[j] = o;
        }
    }
}

// ---------------------------------------------------------------------------
// GEMM kernel
// ---------------------------------------------------------------------------
// CTA tile: 128(M) x 128(N) x 64(K). 256 threads = 8 warps in 2(M) x 4(N).
// Warp tile: 64 x 32 -> 4(m16) x 4(n8) = 16 mma.m16n8k16 per k16 step.
// SMEM: rows of 64 halves = 128 bytes; SW128 swizzle (seg ^= row&7).
// 3 stages x 32KB = 96KB -> 2 CTAs/SM (RF cap: 2 x 256 x 128 regs).

#define A_STAGE_BYTES (BM * 128)              // 16 KB
#define B_STAGE_BYTES (BN * 128)              // 16 KB
#define STAGE_BYTES   (A_STAGE_BYTES + B_STAGE_BYTES)  // 32 KB
#define SMEM_BYTES    (STAGES * STAGE_BYTES)  // 96 KB

__global__ void __launch_bounds__(NTHREADS, 2)
binlinear_gemm_kernel(const float* __restrict__ bias, float* __restrict__ out) {
    extern __shared__ char smem[];
    uint32_t smem_u32;
    asm("{ .reg .u64 t; cvta.to.shared.u64 t, %1; cvt.u32.u64 %0, t; }"
        : "=r"(smem_u32) : "l"(smem));

    const int tid  = threadIdx.x;
    const int lane = tid & 31;
    const int wid  = tid >> 5;
    const int warp_m = (wid >> 2) * 64;   // 0 or 64
    const int warp_n = (wid & 3) * 32;    // 0,32,64,96

    const int m0 = blockIdx.y * BM;
    const int n0 = blockIdx.x * BN;

    // ---- cp.async stage loader (monolithic burst, as in R8/R13) -----------
    auto load_stage = [&](int s, int kt) {
        const uint32_t a_base = smem_u32 + s * STAGE_BYTES;
        const uint32_t b_base = a_base + A_STAGE_BYTES;
        const __half* gA = g_A + (size_t)m0 * K_DIM + kt * BK;
        const __half* gB = g_B + (size_t)n0 * K_DIM + kt * BK;
#pragma unroll
        for (int i = 0; i < 4; ++i) {              // A: 1024 16B chunks
            int cid = tid + i * NTHREADS;
            int row = cid >> 3, seg = cid & 7;
            const __half* src = gA + (size_t)row * K_DIM + seg * 8;
            uint32_t dst = a_base + row * 128 + ((seg ^ (row & 7)) << 4);
            asm volatile("cp.async.cg.shared.global [%0], [%1], 16;\n"
                         :: "r"(dst), "l"(src));
        }
#pragma unroll
        for (int i = 0; i < 4; ++i) {              // B: 1024 16B chunks
            int cid = tid + i * NTHREADS;
            int row = cid >> 3, seg = cid & 7;
            const __half* src = gB + (size_t)row * K_DIM + seg * 8;
            uint32_t dst = b_base + row * 128 + ((seg ^ (row & 7)) << 4);
            asm volatile("cp.async.cg.shared.global [%0], [%1], 16;\n"
                         :: "r"(dst), "l"(src));
        }
    };

    // ---- ldmatrix lane addressing -----------------------------------------
    // A (no trans), x4 -> (m0-7,klo),(m8-15,klo),(m0-7,khi),(m8-15,khi)
    const int a_g  = lane >> 3;
    const int a_row_in = (lane & 7) + (a_g & 1) * 8;
    const int a_hi = a_g >> 1;                 // +8 halves in k
    // B (no trans; smem [n][k] k-contiguous = mma B layout),
    // x4 -> (n0-7,klo),(n0-7,khi),(n8-15,klo),(n8-15,khi)
    const int b_row_in = (lane & 7) + ((a_g >> 1) & 1) * 8;
    const int b_hi = a_g & 1;
    const int sxor = lane & 7;

    uint32_t a_row_off[4];
#pragma unroll
    for (int mi = 0; mi < 4; ++mi)
        a_row_off[mi] = (uint32_t)(warp_m + mi * 16 + a_row_in) * 128;
    uint32_t b_row_off[2];
#pragma unroll
    for (int nj = 0; nj < 2; ++nj)
        b_row_off[nj] = (uint32_t)(warp_n + nj * 16 + b_row_in) * 128;

    float acc[4][4][4];
#pragma unroll
    for (int mi = 0; mi < 4; ++mi)
#pragma unroll
        for (int nk = 0; nk < 4; ++nk)
#pragma unroll
            for (int r = 0; r < 4; ++r) acc[mi][nk][r] = 0.0f;

    // ---- one k16 compute step, internally pipelined -----------------------
    // Order: bf0, bf1, af0 -> [MMA(mi) under ldmatrix af(mi+1)] x4.
    auto compute_ks = [&](uint32_t a_base, uint32_t b_base, int ks) {
        uint32_t af[4][4];
        uint32_t bf[2][4];
#pragma unroll
        for (int nj = 0; nj < 2; ++nj) {
            uint32_t addr = b_base + b_row_off[nj]
                          + ((uint32_t)((ks * 2 + b_hi) ^ sxor) << 4);
            asm volatile(
                "ldmatrix.sync.aligned.m8n8.x4.shared.b16 {%0,%1,%2,%3}, [%4];\n"
                : "=r"(bf[nj][0]), "=r"(bf[nj][1]),
                  "=r"(bf[nj][2]), "=r"(bf[nj][3])
                : "r"(addr));
        }
        {
            uint32_t addr = a_base + a_row_off[0]
                          + ((uint32_t)((ks * 2 + a_hi) ^ sxor) << 4);
            asm volatile(
                "ldmatrix.sync.aligned.m8n8.x4.shared.b16 {%0,%1,%2,%3}, [%4];\n"
                : "=r"(af[0][0]), "=r"(af[0][1]),
                  "=r"(af[0][2]), "=r"(af[0][3])
                : "r"(addr));
        }
#pragma unroll
        for (int mi = 0; mi < 4; ++mi) {
            if (mi < 3) {
                uint32_t addr = a_base + a_row_off[mi + 1]
                              + ((uint32_t)((ks * 2 + a_hi) ^ sxor) << 4);
                asm volatile(
                    "ldmatrix.sync.aligned.m8n8.x4.shared.b16 {%0,%1,%2,%3}, [%4];\n"
                    : "=r"(af[mi + 1][0]), "=r"(af[mi + 1][1]),
                      "=r"(af[mi + 1][2]), "=r"(af[mi + 1][3])
                    : "r"(addr));
            }
#pragma unroll
            for (int nk = 0; nk < 4; ++nk) {
                const int nj = nk >> 1;
                const int sub = (nk & 1) * 2;
                asm volatile(
                    "mma.sync.aligned.m16n8k16.row.col.f32.f16.f16.f32 "
                    "{%0,%1,%2,%3}, {%4,%5,%6,%7}, {%8,%9}, {%0,%1,%2,%3};\n"
                    : "+f"(acc[mi][nk][0]), "+f"(acc[mi][nk][1]),
                      "+f"(acc[mi][nk][2]), "+f"(acc[mi][nk][3])
                    : "r"(af[mi][0]), "r"(af[mi][1]),
                      "r"(af[mi][2]), "r"(af[mi][3]),
                      "r"(bf[nj][sub]), "r"(bf[nj][sub + 1]));
            }
        }
    };

    // ---- prologue: preload 2 stages ---------------------------------------
#pragma unroll
    for (int s = 0; s < STAGES - 1; ++s) {
        load_stage(s, s);
        asm volatile("cp.async.commit_group;\n");
    }

    // ---- mainloop ----------------------------------------------------------
    int stage = 0;
    for (int kt = 0; kt < KTILES; ++kt) {
        asm volatile("cp.async.wait_group %0;\n" :: "n"(STAGES - 2));
        __syncthreads();

        const int ld = kt + STAGES - 1;
        int lds = stage + (STAGES - 1);
        if (lds >= STAGES) lds -= STAGES;

        const uint32_t a_base = smem_u32 + stage * STAGE_BYTES;
        const uint32_t b_base = a_base + A_STAGE_BYTES;
        if (++stage == STAGES) stage = 0;

        // ks=0 first, then the load burst (commit immediately -> R13
        // accounting), then remaining k-steps.
        compute_ks(a_base, b_base, 0);

        if (ld < KTILES) load_stage(lds, ld);
        asm volatile("cp.async.commit_group;\n");

        compute_ks(a_base, b_base, 1);
        compute_ks(a_base, b_base, 2);
        compute_ks(a_base, b_base, 3);
    }

    // ---- epilogue: bias + fp32 store --------------------------------------
    float bcol[4][2];
#pragma unroll
    for (int nk = 0; nk < 4; ++nk) {
        const int c = n0 + warp_n + nk * 8 + (lane & 3) * 2;
        bcol[nk][0] = bias[c];
        bcol[nk][1] = bias[c + 1];
    }
#pragma unroll
    for (int mi = 0; mi < 4; ++mi) {
        const int r0 = m0 + warp_m + mi * 16 + (lane >> 2);
#pragma unroll
        for (int nk = 0; nk < 4; ++nk) {
            const int c = n0 + warp_n + nk * 8 + (lane & 3) * 2;
            float2 v;
            v.x = acc[mi][nk][0] + bcol[nk][0];
            v.y = acc[mi][nk][1] + bcol[nk][1];
            *reinterpret_cast<float2*>(&out[(size_t)r0 * N_DIM + c]) = v;
            v.x = acc[mi][nk][2] + bcol[nk][0];
            v.y = acc[mi][nk][3] + bcol[nk][1];
            *reinterpret_cast<float2*>(&out[(size_t)(r0 + 8) * N_DIM + c]) = v;
        }
    }
}

// ---------------------------------------------------------------------------
// Launch
// ---------------------------------------------------------------------------

extern "C" void kernel_launch(void* const* d_in, const int* in_sizes, int n_in,
                              void* d_out, int out_size) {
    const float* x    = (const float*)d_in[0];
    const float* w    = (const float*)d_in[1];
    const float* bias = (const float*)d_in[2];
    float* out        = (float*)d_out;

    convert_both_kernel<<<3072, 256>>>(x, w);

    cudaFuncSetAttribute(binlinear_gemm_kernel,
                         cudaFuncAttributeMaxDynamicSharedMemorySize,
                         SMEM_BYTES);

    dim3 grid(N_DIM / BN, M_DIM / BM);   // (32, 64)
    binlinear_gemm_kernel<<<grid, NTHREADS, SMEM_BYTES>>>(bias, out);
}

// round 16
// speedup vs baseline: 1.1024x; 1.0034x over previous
#include <cuda_runtime.h>
#include <cuda_fp16.h>
#include <cstdint>

// BinarizedLinear: out[M,N] = x[M,K] @ sign(W)[N,K]^T + bias[N]
// M=8192, N=4096, K=4096, fp32 in/out.
//
// sm_103 (non-'a') PTX target -> no tcgen05; legacy mma.sync path.
// fp16 data (sign(W) exact; x rounded -> rel_err ~2e-4, fp32 accum).
//
// Round 16: GEMM frozen at R13/R15 (634.7us total, GEMM 586us, tensor=77.4%,
// proven co-bound on HMMA issue + smem crossbar at 2048cyc/stage-pair each;
// R7/R14/R15 experiments show scheduling is already optimal). This round
// targets the remaining ~48us: convert kernel gets a static block-range
// split (no per-iteration branch; both regions exactly 16 iters/thread) and
// __ldcs/__stcs streaming hints (single-touch data, evict-first).

#define M_DIM 8192
#define N_DIM 4096
#define K_DIM 4096

#define BM 128
#define BN 128
#define BK 64
#define STAGES 3
#define KTILES (K_DIM / BK)   // 64
#define NTHREADS 256

// fp16 scratch (allocation-free: __device__ globals)
__device__ __half g_A[(size_t)M_DIM * K_DIM];   // 64 MB
__device__ __half g_B[(size_t)N_DIM * K_DIM];   // 32 MB

// ---------------------------------------------------------------------------
// Conversion kernel: blocks [0,2048) convert x -> g_A (16 iters/thread),
// blocks [2048,3072) convert sign(w) -> g_B (16 iters/thread). Streaming
// loads/stores (single-touch).
// ---------------------------------------------------------------------------

#define XBLOCKS 2048
#define WBLOCKS 1024
#define CVT_BLOCKS (XBLOCKS + WBLOCKS)

__device__ __forceinline__ float signf_strict(float v) {
    return (v > 0.0f) ? 1.0f : ((v < 0.0f) ? -1.0f : 0.0f);
}

__global__ void __launch_bounds__(256)
convert_both_kernel(const float* __restrict__ x, const float* __restrict__ w) {
    const int b = blockIdx.x;
    if (b < XBLOCKS) {
        // x region: 8192*4096/4 = 8,388,608 float4 over 2048*256 threads.
        const float4* in = (const float4*)x;
        uint2* outp = (uint2*)g_A;
        size_t base = (size_t)b * 256 + threadIdx.x;
        const size_t stride = (size_t)XBLOCKS * 256;
#pragma unroll 4
        for (int it = 0; it < 16; ++it) {
            size_t i = base + (size_t)it * stride;
            float4 v = __ldcs(&in[i]);
            __half2 h0 = __floats2half2_rn(v.x, v.y);
            __half2 h1 = __floats2half2_rn(v.z, v.w);
            uint2 o;
            o.x = *reinterpret_cast<uint32_t*>(&h0);
            o.y = *reinterpret_cast<uint32_t*>(&h1);
            __stcs(&outp[i], o);
        }
    } else {
        // w region: 4096*4096/4 = 4,194,304 float4 over 1024*256 threads.
        const float4* in = (const float4*)w;
        uint2* outp = (uint2*)g_B;
        size_t base = (size_t)(b - XBLOCKS) * 256 + threadIdx.x;
        const size_t stride = (size_t)WBLOCKS * 256;
#pragma unroll 4
        for (int it = 0; it < 16; ++it) {
            size_t i = base + (size_t)it * stride;
            float4 v = __ldcs(&in[i]);
            __half2 h0 = __floats2half2_rn(signf_strict(v.x), signf_strict(v.y));
            __half2 h1 = __floats2half2_rn(signf_strict(v.z), signf_strict(v.w));
            uint2 o;
            o.x = *reinterpret_cast<uint32_t*>(&h0);
            o.y = *reinterpret_cast<uint32_t*>(&h1);
            __stcs(&outp[i], o);
        }
    }
}

// ---------------------------------------------------------------------------
// GEMM kernel (frozen R13/R15)
// ---------------------------------------------------------------------------
// CTA tile: 128(M) x 128(N) x 64(K). 256 threads = 8 warps in 2(M) x 4(N).
// Warp tile: 64 x 32 -> 4(m16) x 4(n8) = 16 mma.m16n8k16 per k16 step.
// SMEM: rows of 64 halves = 128 bytes; SW128 swizzle (seg ^= row&7).
// 3 stages x 32KB = 96KB -> 2 CTAs/SM (RF cap: 2 x 256 x 128 regs).

#define A_STAGE_BYTES (BM * 128)              // 16 KB
#define B_STAGE_BYTES (BN * 128)              // 16 KB
#define STAGE_BYTES   (A_STAGE_BYTES + B_STAGE_BYTES)  // 32 KB
#define SMEM_BYTES    (STAGES * STAGE_BYTES)  // 96 KB

__global__ void __launch_bounds__(NTHREADS, 2)
binlinear_gemm_kernel(const float* __restrict__ bias, float* __restrict__ out) {
    extern __shared__ char smem[];
    uint32_t smem_u32;
    asm("{ .reg .u64 t; cvta.to.shared.u64 t, %1; cvt.u32.u64 %0, t; }"
        : "=r"(smem_u32) : "l"(smem));

    const int tid  = threadIdx.x;
    const int lane = tid & 31;
    const int wid  = tid >> 5;
    const int warp_m = (wid >> 2) * 64;   // 0 or 64
    const int warp_n = (wid & 3) * 32;    // 0,32,64,96

    const int m0 = blockIdx.y * BM;
    const int n0 = blockIdx.x * BN;

    // ---- cp.async stage loader --------------------------------------------
    auto load_stage = [&](int s, int kt) {
        const uint32_t a_base = smem_u32 + s * STAGE_BYTES;
        const uint32_t b_base = a_base + A_STAGE_BYTES;
        const __half* gA = g_A + (size_t)m0 * K_DIM + kt * BK;
        const __half* gB = g_B + (size_t)n0 * K_DIM + kt * BK;
#pragma unroll
        for (int i = 0; i < 4; ++i) {              // A: 1024 16B chunks
            int cid = tid + i * NTHREADS;
            int row = cid >> 3, seg = cid & 7;
            const __half* src = gA + (size_t)row * K_DIM + seg * 8;
            uint32_t dst = a_base + row * 128 + ((seg ^ (row & 7)) << 4);
            asm volatile("cp.async.cg.shared.global [%0], [%1], 16;\n"
                         :: "r"(dst), "l"(src));
        }
#pragma unroll
        for (int i = 0; i < 4; ++i) {              // B: 1024 16B chunks
            int cid = tid + i * NTHREADS;
            int row = cid >> 3, seg = cid & 7;
            const __half* src = gB + (size_t)row * K_DIM + seg * 8;
            uint32_t dst = b_base + row * 128 + ((seg ^ (row & 7)) << 4);
            asm volatile("cp.async.cg.shared.global [%0], [%1], 16;\n"
                         :: "r"(dst), "l"(src));
        }
    };

    // ---- ldmatrix lane addressing -----------------------------------------
    const int a_g  = lane >> 3;
    const int a_row_in = (lane & 7) + (a_g & 1) * 8;
    const int a_hi = a_g >> 1;
    const int b_row_in = (lane & 7) + ((a_g >> 1) & 1) * 8;
    const int b_hi = a_g & 1;
    const int sxor = lane & 7;

    uint32_t a_row_off[4];
#pragma unroll
    for (int mi = 0; mi < 4; ++mi)
        a_row_off[mi] = (uint32_t)(warp_m + mi * 16 + a_row_in) * 128;
    uint32_t b_row_off[2];
#pragma unroll
    for (int nj = 0; nj < 2; ++nj)
        b_row_off[nj] = (uint32_t)(warp_n + nj * 16 + b_row_in) * 128;

    float acc[4][4][4];
#pragma unroll
    for (int mi = 0; mi < 4; ++mi)
#pragma unroll
        for (int nk = 0; nk < 4; ++nk)
#pragma unroll
            for (int r = 0; r < 4; ++r) acc[mi][nk][r] = 0.0f;

    // ---- one k16 compute step ---------------------------------------------
    auto compute_ks = [&](uint32_t a_base, uint32_t b_base, int ks) {
        uint32_t af[4][4];
        uint32_t bf[2][4];
#pragma unroll
        for (int nj = 0; nj < 2; ++nj) {
            uint32_t addr = b_base + b_row_off[nj]
                          + ((uint32_t)((ks * 2 + b_hi) ^ sxor) << 4);
            asm volatile(
                "ldmatrix.sync.aligned.m8n8.x4.shared.b16 {%0,%1,%2,%3}, [%4];\n"
                : "=r"(bf[nj][0]), "=r"(bf[nj][1]),
                  "=r"(bf[nj][2]), "=r"(bf[nj][3])
                : "r"(addr));
        }
#pragma unroll
        for (int mi = 0; mi < 4; ++mi) {
            uint32_t addr = a_base + a_row_off[mi]
                          + ((uint32_t)((ks * 2 + a_hi) ^ sxor) << 4);
            asm volatile(
                "ldmatrix.sync.aligned.m8n8.x4.shared.b16 {%0,%1,%2,%3}, [%4];\n"
                : "=r"(af[mi][0]), "=r"(af[mi][1]),
                  "=r"(af[mi][2]), "=r"(af[mi][3])
                : "r"(addr));
        }
#pragma unroll
        for (int mi = 0; mi < 4; ++mi) {
#pragma unroll
            for (int nk = 0; nk < 4; ++nk) {
                const int nj = nk >> 1;
                const int sub = (nk & 1) * 2;
                asm volatile(
                    "mma.sync.aligned.m16n8k16.row.col.f32.f16.f16.f32 "
                    "{%0,%1,%2,%3}, {%4,%5,%6,%7}, {%8,%9}, {%0,%1,%2,%3};\n"
                    : "+f"(acc[mi][nk][0]), "+f"(acc[mi][nk][1]),
                      "+f"(acc[mi][nk][2]), "+f"(acc[mi][nk][3])
                    : "r"(af[mi][0]), "r"(af[mi][1]),
                      "r"(af[mi][2]), "r"(af[mi][3]),
                      "r"(bf[nj][sub]), "r"(bf[nj][sub + 1]));
            }
        }
    };

    // ---- prologue: preload 2 stages ---------------------------------------
#pragma unroll
    for (int s = 0; s < STAGES - 1; ++s) {
        load_stage(s, s);
        asm volatile("cp.async.commit_group;\n");
    }

    // ---- mainloop ----------------------------------------------------------
    int stage = 0;
    for (int kt = 0; kt < KTILES; ++kt) {
        asm volatile("cp.async.wait_group %0;\n" :: "n"(STAGES - 2));
        __syncthreads();

        const int ld = kt + STAGES - 1;
        int lds = stage + (STAGES - 1);
        if (lds >= STAGES) lds -= STAGES;

        const uint32_t a_base = smem_u32 + stage * STAGE_BYTES;
        const uint32_t b_base = a_base + A_STAGE_BYTES;
        if (++stage == STAGES) stage = 0;

        compute_ks(a_base, b_base, 0);

        if (ld < KTILES) load_stage(lds, ld);
        asm volatile("cp.async.commit_group;\n");

        compute_ks(a_base, b_base, 1);
        compute_ks(a_base, b_base, 2);
        compute_ks(a_base, b_base, 3);
    }

    // ---- epilogue: bias + fp32 store --------------------------------------
    float bcol[4][2];
#pragma unroll
    for (int nk = 0; nk < 4; ++nk) {
        const int c = n0 + warp_n + nk * 8 + (lane & 3) * 2;
        bcol[nk][0] = bias[c];
        bcol[nk][1] = bias[c + 1];
    }
#pragma unroll
    for (int mi = 0; mi < 4; ++mi) {
        const int r0 = m0 + warp_m + mi * 16 + (lane >> 2);
#pragma unroll
        for (int nk = 0; nk < 4; ++nk) {
            const int c = n0 + warp_n + nk * 8 + (lane & 3) * 2;
            float2 v;
            v.x = acc[mi][nk][0] + bcol[nk][0];
            v.y = acc[mi][nk][1] + bcol[nk][1];
            *reinterpret_cast<float2*>(&out[(size_t)r0 * N_DIM + c]) = v;
            v.x = acc[mi][nk][2] + bcol[nk][0];
            v.y = acc[mi][nk][3] + bcol[nk][1];
            *reinterpret_cast<float2*>(&out[(size_t)(r0 + 8) * N_DIM + c]) = v;
        }
    }
}

// ---------------------------------------------------------------------------
// Launch
// ---------------------------------------------------------------------------

extern "C" void kernel_launch(void* const* d_in, const int* in_sizes, int n_in,
                              void* d_out, int out_size) {
    const float* x    = (const float*)d_in[0];
    const float* w    = (const float*)d_in[1];
    const float* bias = (const float*)d_in[2];
    float* out        = (float*)d_out;

    convert_both_kernel<<<CVT_BLOCKS, 256>>>(x, w);

    cudaFuncSetAttribute(binlinear_gemm_kernel,
                         cudaFuncAttributeMaxDynamicSharedMemorySize,
                         SMEM_BYTES);

    dim3 grid(N_DIM / BN, M_DIM / BM);   // (32, 64)
    binlinear_gemm_kernel<<<grid, NTHREADS, SMEM_BYTES>>>(bias, out);
}

// round 17
// speedup vs baseline: 1.1145x; 1.0110x over previous
#include <cuda_runtime.h>
#include <cuda_fp16.h>
#include <cstdint>

// BinarizedLinear: out[M,N] = x[M,K] @ sign(W)[N,K]^T + bias[N]
// M=8192, N=4096, K=4096, fp32 in/out.
//
// sm_103 (non-'a') PTX target -> no tcgen05; legacy mma.sync path.
// fp16 data (sign(W) exact; x rounded -> rel_err ~2e-4, fp32 accum).
//
// Round 17: GEMM mainloop frozen (converged: fixed HMMA work = ~451us busy,
// crossbar and tensor issue both ~100% subscribed per stage-pair; R7/R9/
// R14/R15 bracket the design space -- every restructuring hits the RF or
// smem wall). Residual shavings only:
//  (1) bias slice staged into smem via cp.async in the prologue; epilogue
//      reads LDS instead of a dependent LDG chain per CTA.
//  (2) convert loop fully unrolled.

#define M_DIM 8192
#define N_DIM 4096
#define K_DIM 4096

#define BM 128
#define BN 128
#define BK 64
#define STAGES 3
#define KTILES (K_DIM / BK)   // 64
#define NTHREADS 256

// fp16 scratch (allocation-free: __device__ globals)
__device__ __half g_A[(size_t)M_DIM * K_DIM];   // 64 MB
__device__ __half g_B[(size_t)N_DIM * K_DIM];   // 32 MB

// ---------------------------------------------------------------------------
// Conversion kernel: blocks [0,2048) convert x -> g_A (16 iters/thread),
// blocks [2048,3072) convert sign(w) -> g_B (16 iters/thread). Streaming
// loads/stores (single-touch).
// ---------------------------------------------------------------------------

#define XBLOCKS 2048
#define WBLOCKS 1024
#define CVT_BLOCKS (XBLOCKS + WBLOCKS)

__device__ __forceinline__ float signf_strict(float v) {
    return (v > 0.0f) ? 1.0f : ((v < 0.0f) ? -1.0f : 0.0f);
}

__global__ void __launch_bounds__(256)
convert_both_kernel(const float* __restrict__ x, const float* __restrict__ w) {
    const int b = blockIdx.x;
    if (b < XBLOCKS) {
        const float4* in = (const float4*)x;
        uint2* outp = (uint2*)g_A;
        size_t base = (size_t)b * 256 + threadIdx.x;
        const size_t stride = (size_t)XBLOCKS * 256;
#pragma unroll
        for (int it = 0; it < 16; ++it) {
            size_t i = base + (size_t)it * stride;
            float4 v = __ldcs(&in[i]);
            __half2 h0 = __floats2half2_rn(v.x, v.y);
            __half2 h1 = __floats2half2_rn(v.z, v.w);
            uint2 o;
            o.x = *reinterpret_cast<uint32_t*>(&h0);
            o.y = *reinterpret_cast<uint32_t*>(&h1);
            __stcs(&outp[i], o);
        }
    } else {
        const float4* in = (const float4*)w;
        uint2* outp = (uint2*)g_B;
        size_t base = (size_t)(b - XBLOCKS) * 256 + threadIdx.x;
        const size_t stride = (size_t)WBLOCKS * 256;
#pragma unroll
        for (int it = 0; it < 16; ++it) {
            size_t i = base + (size_t)it * stride;
            float4 v = __ldcs(&in[i]);
            __half2 h0 = __floats2half2_rn(signf_strict(v.x), signf_strict(v.y));
            __half2 h1 = __floats2half2_rn(signf_strict(v.z), signf_strict(v.w));
            uint2 o;
            o.x = *reinterpret_cast<uint32_t*>(&h0);
            o.y = *reinterpret_cast<uint32_t*>(&h1);
            __stcs(&outp[i], o);
        }
    }
}

// ---------------------------------------------------------------------------
// GEMM kernel (mainloop frozen at R13/R15/R16)
// ---------------------------------------------------------------------------
// CTA tile: 128(M) x 128(N) x 64(K). 256 threads = 8 warps in 2(M) x 4(N).
// Warp tile: 64 x 32 -> 4(m16) x 4(n8) = 16 mma.m16n8k16 per k16 step.
// SMEM: rows of 64 halves = 128 bytes; SW128 swizzle (seg ^= row&7).
// 3 stages x 32KB + 512B bias slice = 96.5KB -> 2 CTAs/SM.

#define A_STAGE_BYTES (BM * 128)              // 16 KB
#define B_STAGE_BYTES (BN * 128)              // 16 KB
#define STAGE_BYTES   (A_STAGE_BYTES + B_STAGE_BYTES)  // 32 KB
#define BIAS_OFF      (STAGES * STAGE_BYTES)  // 96 KB
#define SMEM_BYTES    (BIAS_OFF + BN * 4)     // + 512 B

__global__ void __launch_bounds__(NTHREADS, 2)
binlinear_gemm_kernel(const float* __restrict__ bias, float* __restrict__ out) {
    extern __shared__ char smem[];
    uint32_t smem_u32;
    asm("{ .reg .u64 t; cvta.to.shared.u64 t, %1; cvt.u32.u64 %0, t; }"
        : "=r"(smem_u32) : "l"(smem));

    const int tid  = threadIdx.x;
    const int lane = tid & 31;
    const int wid  = tid >> 5;
    const int warp_m = (wid >> 2) * 64;   // 0 or 64
    const int warp_n = (wid & 3) * 32;    // 0,32,64,96

    const int m0 = blockIdx.y * BM;
    const int n0 = blockIdx.x * BN;

    // ---- cp.async stage loader --------------------------------------------
    auto load_stage = [&](int s, int kt) {
        const uint32_t a_base = smem_u32 + s * STAGE_BYTES;
        const uint32_t b_base = a_base + A_STAGE_BYTES;
        const __half* gA = g_A + (size_t)m0 * K_DIM + kt * BK;
        const __half* gB = g_B + (size_t)n0 * K_DIM + kt * BK;
#pragma unroll
        for (int i = 0; i < 4; ++i) {              // A: 1024 16B chunks
            int cid = tid + i * NTHREADS;
            int row = cid >> 3, seg = cid & 7;
            const __half* src = gA + (size_t)row * K_DIM + seg * 8;
            uint32_t dst = a_base + row * 128 + ((seg ^ (row & 7)) << 4);
            asm volatile("cp.async.cg.shared.global [%0], [%1], 16;\n"
                         :: "r"(dst), "l"(src));
        }
#pragma unroll
        for (int i = 0; i < 4; ++i) {              // B: 1024 16B chunks
            int cid = tid + i * NTHREADS;
            int row = cid >> 3, seg = cid & 7;
            const __half* src = gB + (size_t)row * K_DIM + seg * 8;
            uint32_t dst = b_base + row * 128 + ((seg ^ (row & 7)) << 4);
            asm volatile("cp.async.cg.shared.global [%0], [%1], 16;\n"
                         :: "r"(dst), "l"(src));
        }
    };

    // ---- ldmatrix lane addressing -----------------------------------------
    const int a_g  = lane >> 3;
    const int a_row_in = (lane & 7) + (a_g & 1) * 8;
    const int a_hi = a_g >> 1;
    const int b_row_in = (lane & 7) + ((a_g >> 1) & 1) * 8;
    const int b_hi = a_g & 1;
    const int sxor = lane & 7;

    uint32_t a_row_off[4];
#pragma unroll
    for (int mi = 0; mi < 4; ++mi)
        a_row_off[mi] = (uint32_t)(warp_m + mi * 16 + a_row_in) * 128;
    uint32_t b_row_off[2];
#pragma unroll
    for (int nj = 0; nj < 2; ++nj)
        b_row_off[nj] = (uint32_t)(warp_n + nj * 16 + b_row_in) * 128;

    float acc[4][4][4];
#pragma unroll
    for (int mi = 0; mi < 4; ++mi)
#pragma unroll
        for (int nk = 0; nk < 4; ++nk)
#pragma unroll
            for (int r = 0; r < 4; ++r) acc[mi][nk][r] = 0.0f;

    // ---- one k16 compute step ---------------------------------------------
    auto compute_ks = [&](uint32_t a_base, uint32_t b_base, int ks) {
        uint32_t af[4][4];
        uint32_t bf[2][4];
#pragma unroll
        for (int nj = 0; nj < 2; ++nj) {
            uint32_t addr = b_base + b_row_off[nj]
                          + ((uint32_t)((ks * 2 + b_hi) ^ sxor) << 4);
            asm volatile(
                "ldmatrix.sync.aligned.m8n8.x4.shared.b16 {%0,%1,%2,%3}, [%4];\n"
                : "=r"(bf[nj][0]), "=r"(bf[nj][1]),
                  "=r"(bf[nj][2]), "=r"(bf[nj][3])
                : "r"(addr));
        }
#pragma unroll
        for (int mi = 0; mi < 4; ++mi) {
            uint32_t addr = a_base + a_row_off[mi]
                          + ((uint32_t)((ks * 2 + a_hi) ^ sxor) << 4);
            asm volatile(
                "ldmatrix.sync.aligned.m8n8.x4.shared.b16 {%0,%1,%2,%3}, [%4];\n"
                : "=r"(af[mi][0]), "=r"(af[mi][1]),
                  "=r"(af[mi][2]), "=r"(af[mi][3])
                : "r"(addr));
        }
#pragma unroll
        for (int mi = 0; mi < 4; ++mi) {
#pragma unroll
            for (int nk = 0; nk < 4; ++nk) {
                const int nj = nk >> 1;
                const int sub = (nk & 1) * 2;
                asm volatile(
                    "mma.sync.aligned.m16n8k16.row.col.f32.f16.f16.f32 "
                    "{%0,%1,%2,%3}, {%4,%5,%6,%7}, {%8,%9}, {%0,%1,%2,%3};\n"
                    : "+f"(acc[mi][nk][0]), "+f"(acc[mi][nk][1]),
                      "+f"(acc[mi][nk][2]), "+f"(acc[mi][nk][3])
                    : "r"(af[mi][0]), "r"(af[mi][1]),
                      "r"(af[mi][2]), "r"(af[mi][3]),
                      "r"(bf[nj][sub]), "r"(bf[nj][sub + 1]));
            }
        }
    };

    // ---- prologue: preload 2 stages + bias slice --------------------------
    {
        // bias slice: 128 floats = 512 B; one 4B cp.async per thread of the
        // first half-block (tid < 128). Joins stage-0's commit group.
        if (tid < BN) {
            const float* bsrc = bias + n0 + tid;
            uint32_t bdst = smem_u32 + BIAS_OFF + tid * 4;
            asm volatile("cp.async.ca.shared.global [%0], [%1], 4;\n"
                         :: "r"(bdst), "l"(bsrc));
        }
        load_stage(0, 0);
        asm volatile("cp.async.commit_group;\n");
        load_stage(1, 1);
        asm volatile("cp.async.commit_group;\n");
    }

    // ---- mainloop ----------------------------------------------------------
    int stage = 0;
    for (int kt = 0; kt < KTILES; ++kt) {
        asm volatile("cp.async.wait_group %0;\n" :: "n"(STAGES - 2));
        __syncthreads();

        const int ld = kt + STAGES - 1;
        int lds = stage + (STAGES - 1);
        if (lds >= STAGES) lds -= STAGES;

        const uint32_t a_base = smem_u32 + stage * STAGE_BYTES;
        const uint32_t b_base = a_base + A_STAGE_BYTES;
        if (++stage == STAGES) stage = 0;

        compute_ks(a_base, b_base, 0);

        if (ld < KTILES) load_stage(lds, ld);
        asm volatile("cp.async.commit_group;\n");

        compute_ks(a_base, b_base, 1);
        compute_ks(a_base, b_base, 2);
        compute_ks(a_base, b_base, 3);
    }

    // ---- epilogue: bias (from smem) + fp32 store --------------------------
    const float* bsm = reinterpret_cast<const float*>(smem + BIAS_OFF);
    float bcol[4][2];
#pragma unroll
    for (int nk = 0; nk < 4; ++nk) {
        const int cl = warp_n + nk * 8 + (lane & 3) * 2;
        bcol[nk][0] = bsm[cl];
        bcol[nk][1] = bsm[cl + 1];
    }
#pragma unroll
    for (int mi = 0; mi < 4; ++mi) {
        const int r0 = m0 + warp_m + mi * 16 + (lane >> 2);
#pragma unroll
        for (int nk = 0; nk < 4; ++nk) {
            const int c = n0 + warp_n + nk * 8 + (lane & 3) * 2;
            float2 v;
            v.x = acc[mi][nk][0] + bcol[nk][0];
            v.y = acc[mi][nk][1] + bcol[nk][1];
            *reinterpret_cast<float2*>(&out[(size_t)r0 * N_DIM + c]) = v;
            v.x = acc[mi][nk][2] + bcol[nk][0];
            v.y = acc[mi][nk][3] + bcol[nk][1];
            *reinterpret_cast<float2*>(&out[(size_t)(r0 + 8) * N_DIM + c]) = v;
        }
    }
}

// ---------------------------------------------------------------------------
// Launch
// ---------------------------------------------------------------------------

extern "C" void kernel_launch(void* const* d_in, const int* in_sizes, int n_in,
                              void* d_out, int out_size) {
    const float* x    = (const float*)d_in[0];
    const float* w    = (const float*)d_in[1];
    const float* bias = (const float*)d_in[2];
    float* out        = (float*)d_out;

    convert_both_kernel<<<CVT_BLOCKS, 256>>>(x, w);

    cudaFuncSetAttribute(binlinear_gemm_kernel,
                         cudaFuncAttributeMaxDynamicSharedMemorySize,
                         SMEM_BYTES);

    dim3 grid(N_DIM / BN, M_DIM / BM);   // (32, 64)
    binlinear_gemm_kernel<<<grid, NTHREADS, SMEM_BYTES>>>(bias, out);
}